// round 10
// baseline (speedup 1.0000x reference)
#include <cuda_runtime.h>
#include <cstdint>

#define B_ 4
#define L_ 2048
#define D_ 512
#define H_ 8
#define E_ 64

// Projected Q/K/V scratch, [B,H,L,E] (each (b,h) slice is contiguous [L,E]).
__device__ __align__(256) float g_q[B_ * H_ * L_ * E_];
__device__ __align__(256) float g_k[B_ * H_ * L_ * E_];
__device__ __align__(256) float g_v[B_ * H_ * L_ * E_];

// ---------------------------------------------------------------------------
// helpers
// ---------------------------------------------------------------------------
__device__ __forceinline__ uint32_t smem_u32(const void* p) {
    uint32_t a;
    asm("{ .reg .u64 t; cvta.to.shared.u64 t, %1; cvt.u32.u64 %0, t; }"
        : "=r"(a) : "l"(p));
    return a;
}

// Round fp32 -> nearest tf32 (kills the truncation bias of the MMA datapath).
__device__ __forceinline__ uint32_t rna(float x) {
    uint32_t r;
    asm("cvt.rna.tf32.f32 %0, %1;" : "=r"(r) : "f"(x));
    return r;
}

// D = A(16x8,row) * B(8x8,col) + D, tf32 inputs
__device__ __forceinline__ void mma_tf32(float* d, const uint32_t* a, const uint32_t* b) {
    asm volatile(
        "mma.sync.aligned.m16n8k8.row.col.f32.tf32.tf32.f32 "
        "{%0,%1,%2,%3}, {%4,%5,%6,%7}, {%8,%9}, {%0,%1,%2,%3};"
        : "+f"(d[0]), "+f"(d[1]), "+f"(d[2]), "+f"(d[3])
        : "r"(a[0]), "r"(a[1]), "r"(a[2]), "r"(a[3]), "r"(b[0]), "r"(b[1]));
}

__device__ __forceinline__ void cp16(uint32_t dst, const void* src) {
    asm volatile("cp.async.cg.shared.global [%0], [%1], 16;"
                 :: "r"(dst), "l"(src) : "memory");
}
#define CP_COMMIT() asm volatile("cp.async.commit_group;" ::: "memory")
#define CP_WAIT(n)  asm volatile("cp.async.wait_group %0;" :: "n"(n) : "memory")

// streaming (evict-first) stores for the huge attn matrix
__device__ __forceinline__ void st_cs2(float* p, float x, float y) {
    asm volatile("st.global.cs.v2.f32 [%0], {%1, %2};" :: "l"(p), "f"(x), "f"(y) : "memory");
}

// ---------------------------------------------------------------------------
// Kernel 1: QKV projection (1x tf32, RN-rounded operands).
// CTA 128x128, 8 warps (2M x 4N), K=512 in BK=32 chunks, double buffer.
// grid (64, 4, 3), 256 thr.
// ---------------------------------------------------------------------------
static constexpr int PJ_XS = 128 * 36;
static constexpr int PJ_WS = 32 * 136;
static constexpr int PJ_SMEM = (2 * PJ_XS + 2 * PJ_WS) * 4;   // 71680 B

__global__ void __launch_bounds__(256, 2) proj_mma(
    const float* __restrict__ X0, const float* __restrict__ X1,
    const float* __restrict__ X2,
    const float* __restrict__ W0, const float* __restrict__ W1,
    const float* __restrict__ W2,
    const float* __restrict__ b0, const float* __restrict__ b1,
    const float* __restrict__ b2)
{
    extern __shared__ float smf[];
    float* Xs = smf;
    float* Ws = smf + 2 * PJ_XS;
    uint32_t sX = smem_u32(Xs), sW = smem_u32(Ws);

    int z = blockIdx.z;
    const float* X = (z == 0) ? X0 : (z == 1) ? X1 : X2;
    const float* W = (z == 0) ? W0 : (z == 1) ? W1 : W2;
    const float* bias = (z == 0) ? b0 : (z == 1) ? b1 : b2;
    float* dst = (z == 0) ? g_q : (z == 1) ? g_k : g_v;

    int t = threadIdx.x;
    int lane = t & 31, wid = t >> 5;
    int gid = lane >> 2, tg = lane & 3;
    int warpM = wid >> 2, warpN = wid & 3;
    int m0 = blockIdx.x * 128, n0 = blockIdx.y * 128;

    float acc[4][4][4] = {};

    auto stage = [&](int kt, int buf) {
        int k0 = kt * 32;
#pragma unroll
        for (int i = 0; i < 4; i++) {
            int idx = t + i * 256;
            int row = idx >> 3, cc = (idx & 7) * 4;
            cp16(sX + (buf * PJ_XS + row * 36 + cc) * 4,
                 X + (size_t)(m0 + row) * D_ + k0 + cc);
        }
#pragma unroll
        for (int i = 0; i < 4; i++) {
            int idx = t + i * 256;
            int row = idx >> 5, cc = (idx & 31) * 4;
            cp16(sW + (buf * PJ_WS + row * 136 + cc) * 4,
                 W + (size_t)(k0 + row) * D_ + n0 + cc);
        }
    };

    stage(0, 0); CP_COMMIT();
    const int NIT = D_ / 32;                 // 16
    for (int kt = 0; kt < NIT; kt++) {
        int p = kt & 1;
        if (kt + 1 < NIT) { stage(kt + 1, p ^ 1); CP_COMMIT(); CP_WAIT(1); }
        else              { CP_WAIT(0); }
        __syncthreads();

        const float* Ab = Xs + p * PJ_XS;
        const float* Bb = Ws + p * PJ_WS;
#pragma unroll
        for (int ks = 0; ks < 4; ks++) {
            int k0 = ks * 8;
            uint32_t a[4][4], b[4][2];
#pragma unroll
            for (int mt = 0; mt < 4; mt++) {
                const float* pa = Ab + (warpM * 64 + mt * 16 + gid) * 36 + k0 + tg;
                a[mt][0] = rna(pa[0]);
                a[mt][1] = rna(pa[8 * 36]);
                a[mt][2] = rna(pa[4]);
                a[mt][3] = rna(pa[8 * 36 + 4]);
            }
#pragma unroll
            for (int nt = 0; nt < 4; nt++) {
                const float* pb = Bb + (k0 + tg) * 136 + warpN * 32 + nt * 8 + gid;
                b[nt][0] = rna(pb[0]);
                b[nt][1] = rna(pb[4 * 136]);
            }
#pragma unroll
            for (int mt = 0; mt < 4; mt++)
#pragma unroll
                for (int nt = 0; nt < 4; nt++)
                    mma_tf32(acc[mt][nt], a[mt], b[nt]);
        }
        __syncthreads();
    }

#pragma unroll
    for (int mt = 0; mt < 4; mt++) {
        int m = m0 + warpM * 64 + mt * 16 + gid;
        int bb = m >> 11;
        int l  = m & (L_ - 1);
#pragma unroll
        for (int nt = 0; nt < 4; nt++) {
            int n = n0 + warpN * 32 + nt * 8 + tg * 2;
            int h = n >> 6, e = n & 63;
            float2 bi = *reinterpret_cast<const float2*>(bias + n);
            *reinterpret_cast<float2*>(dst + (((size_t)(bb * H_ + h)) * L_ + l) * E_ + e) =
                make_float2(acc[mt][nt][0] + bi.x, acc[mt][nt][1] + bi.y);
            *reinterpret_cast<float2*>(dst + (((size_t)(bb * H_ + h)) * L_ + l + 8) * E_ + e) =
                make_float2(acc[mt][nt][2] + bi.x, acc[mt][nt][3] + bi.y);
        }
    }
}

// ---------------------------------------------------------------------------
// Kernel 2: FUSED scores + softmax + AV, 64-row stripes, 2 CTAs/SM.
// Pass A: stream K tiles (64 cols), accumulate CTA-local row sums of
//         exp(scale*QK^T).  No attn write.
// Pass B: recompute S tiles (bit-identical), normalize in-register, write
//         attn exactly once (streaming stores), stage via Sst, AV-MMA.
// grid (32, 32), 256 threads, 8 warps.
// SMEM (floats): Qs[64][68] | Ks[2][64][68] | Vs[2][64][72] | Sst[64][68]
//                | rowinv[64]  = 106752 B  -> 2 CTAs/SM
// ---------------------------------------------------------------------------
static constexpr int F_KS  = 64 * 68;             // 4352
static constexpr int F_VS  = F_KS + 2 * 64 * 68;  // 13056
static constexpr int F_SST = F_VS + 2 * 64 * 72;  // 22272
static constexpr int F_RI  = F_SST + 64 * 68;     // 26624
static constexpr int F_SMEM = (F_RI + 64) * 4;    // 106752 B

__global__ void __launch_bounds__(256, 2) fused64(float* __restrict__ attn,
                                                  float* __restrict__ out)
{
    extern __shared__ float smf[];
    float* Qs = smf;
    float* Ks = smf + F_KS;
    float* Vs = smf + F_VS;
    float* Sst = smf + F_SST;
    float* rowinv = smf + F_RI;
    uint32_t sQ = smem_u32(Qs), sK = smem_u32(Ks), sV = smem_u32(Vs);

    int t = threadIdx.x;
    int lane = t & 31, wid = t >> 5;
    int gid = lane >> 2, tg = lane & 3;
    int warpM = wid >> 2, warpN = wid & 3;      // S tiling: 2M x 4N (32x16/warp)
    int warpM2 = wid >> 1, warpN2 = wid & 1;    // out tiling: 4M x 2N (16x32/warp)
    int m0 = blockIdx.x * 64, bh = blockIdx.y;
    int bb = bh >> 3, h = bh & 7;

    const float* Q = g_q + (size_t)bh * L_ * E_;
    const float* K = g_k + (size_t)bh * L_ * E_;
    const float* V = g_v + (size_t)bh * L_ * E_;
    float* S = attn + (size_t)bh * L_ * L_;

    // Q stripe: 64 rows, resident whole kernel (1024 float4)
#pragma unroll
    for (int i = 0; i < 4; i++) {
        int idx = t + i * 256;
        int row = idx >> 4, cc = (idx & 15) * 4;
        cp16(sQ + (row * 68 + cc) * 4, Q + (size_t)(m0 + row) * E_ + cc);
    }
    CP_COMMIT();

    auto stageK = [&](int tile, int buf) {
#pragma unroll
        for (int i = 0; i < 4; i++) {
            int idx = t + i * 256;
            int row = idx >> 4, cc = (idx & 15) * 4;
            cp16(sK + (buf * F_KS + row * 68 + cc) * 4,
                 K + (size_t)(tile * 64 + row) * E_ + cc);
        }
    };
    auto stageV = [&](int tile, int buf) {
#pragma unroll
        for (int i = 0; i < 4; i++) {
            int idx = t + i * 256;
            int row = idx >> 4, cc = (idx & 15) * 4;
            cp16(sV + (buf * (64 * 72) + row * 72 + cc) * 4,
                 V + (size_t)(tile * 64 + row) * E_ + cc);
        }
    };

    const float scale = 0.125f;

    // ---------------- pass A: row sums only (no attn write) ----------------
    stageK(0, 0); CP_COMMIT();
    float rowpart[2][2] = {};
    for (int tile = 0; tile < 32; tile++) {
        int p = tile & 1;
        if (tile + 1 < 32) { stageK(tile + 1, p ^ 1); CP_COMMIT(); CP_WAIT(1); }
        else               { CP_WAIT(0); }
        __syncthreads();

        const float* Kb = Ks + p * F_KS;
        float acc[2][2][4] = {};
#pragma unroll
        for (int ks = 0; ks < 8; ks++) {
            int k0 = ks * 8;
            uint32_t a[2][4], b[2][2];
#pragma unroll
            for (int mt = 0; mt < 2; mt++) {
                const float* pa = Qs + (warpM * 32 + mt * 16 + gid) * 68 + k0 + tg;
                a[mt][0] = rna(pa[0]);
                a[mt][1] = rna(pa[8 * 68]);
                a[mt][2] = rna(pa[4]);
                a[mt][3] = rna(pa[8 * 68 + 4]);
            }
#pragma unroll
            for (int nt = 0; nt < 2; nt++) {
                const float* pb = Kb + (warpN * 16 + nt * 8 + gid) * 68 + k0 + tg;
                b[nt][0] = rna(pb[0]);
                b[nt][1] = rna(pb[4]);
            }
#pragma unroll
            for (int mt = 0; mt < 2; mt++)
#pragma unroll
                for (int nt = 0; nt < 2; nt++)
                    mma_tf32(acc[mt][nt], a[mt], b[nt]);
        }
#pragma unroll
        for (int mt = 0; mt < 2; mt++)
#pragma unroll
            for (int nt = 0; nt < 2; nt++) {
                rowpart[mt][0] += __expf(acc[mt][nt][0] * scale)
                                + __expf(acc[mt][nt][1] * scale);
                rowpart[mt][1] += __expf(acc[mt][nt][2] * scale)
                                + __expf(acc[mt][nt][3] * scale);
            }
        __syncthreads();   // buffer p may be restaged next iteration
    }

    // start pass-B prefetch early (targets Ks/Vs, not Sst)
    stageK(0, 0); stageV(0, 0); CP_COMMIT();

    // reduce row sums: over tg lanes, then across the 4 warpN warps via Sst
#pragma unroll
    for (int mt = 0; mt < 2; mt++)
#pragma unroll
        for (int half = 0; half < 2; half++) {
            float v = rowpart[mt][half];
            v += __shfl_xor_sync(0xffffffffu, v, 1);
            v += __shfl_xor_sync(0xffffffffu, v, 2);
            if (tg == 0)
                Sst[warpN * 64 + warpM * 32 + mt * 16 + half * 8 + gid] = v;
        }
    __syncthreads();
    if (t < 64)
        rowinv[t] = 1.0f / (Sst[t] + Sst[64 + t] + Sst[128 + t] + Sst[192 + t]);
    __syncthreads();

    // ---------- pass B: recompute, normalize, write attn once, AV ----------
    float oacc[4][4] = {};
    for (int tile = 0; tile < 32; tile++) {
        int p = tile & 1;
        if (tile + 1 < 32) {
            stageK(tile + 1, p ^ 1); stageV(tile + 1, p ^ 1); CP_COMMIT();
            CP_WAIT(1);
        } else { CP_WAIT(0); }
        __syncthreads();

        const float* Kb = Ks + p * F_KS;
        const float* Vb = Vs + p * (64 * 72);

        // recompute S fragments (identical to pass A)
        float acc[2][2][4] = {};
#pragma unroll
        for (int ks = 0; ks < 8; ks++) {
            int k0 = ks * 8;
            uint32_t a[2][4], b[2][2];
#pragma unroll
            for (int mt = 0; mt < 2; mt++) {
                const float* pa = Qs + (warpM * 32 + mt * 16 + gid) * 68 + k0 + tg;
                a[mt][0] = rna(pa[0]);
                a[mt][1] = rna(pa[8 * 68]);
                a[mt][2] = rna(pa[4]);
                a[mt][3] = rna(pa[8 * 68 + 4]);
            }
#pragma unroll
            for (int nt = 0; nt < 2; nt++) {
                const float* pb = Kb + (warpN * 16 + nt * 8 + gid) * 68 + k0 + tg;
                b[nt][0] = rna(pb[0]);
                b[nt][1] = rna(pb[4]);
            }
#pragma unroll
            for (int mt = 0; mt < 2; mt++)
#pragma unroll
                for (int nt = 0; nt < 2; nt++)
                    mma_tf32(acc[mt][nt], a[mt], b[nt]);
        }

        // normalize in-register, write attn once, stash normalized values
#pragma unroll
        for (int mt = 0; mt < 2; mt++) {
            int rl0 = warpM * 32 + mt * 16 + gid;
            float i0 = rowinv[rl0], i1 = rowinv[rl0 + 8];
#pragma unroll
            for (int nt = 0; nt < 2; nt++) {
                int cc = tile * 64 + warpN * 16 + nt * 8 + tg * 2;
                float p0 = __expf(acc[mt][nt][0] * scale) * i0;
                float p1 = __expf(acc[mt][nt][1] * scale) * i0;
                float p2 = __expf(acc[mt][nt][2] * scale) * i1;
                float p3 = __expf(acc[mt][nt][3] * scale) * i1;
                st_cs2(S + (size_t)(m0 + rl0) * L_ + cc, p0, p1);
                st_cs2(S + (size_t)(m0 + rl0 + 8) * L_ + cc, p2, p3);
                acc[mt][nt][0] = p0; acc[mt][nt][1] = p1;
                acc[mt][nt][2] = p2; acc[mt][nt][3] = p3;
            }
        }

        // stage normalized S tile into Sst (prev AV reads fenced by top sync)
#pragma unroll
        for (int mt = 0; mt < 2; mt++) {
            int rl = warpM * 32 + mt * 16 + gid;
#pragma unroll
            for (int nt = 0; nt < 2; nt++) {
                int cc = warpN * 16 + nt * 8 + tg * 2;
                *reinterpret_cast<float2*>(Sst + rl * 68 + cc) =
                    make_float2(acc[mt][nt][0], acc[mt][nt][1]);
                *reinterpret_cast<float2*>(Sst + (rl + 8) * 68 + cc) =
                    make_float2(acc[mt][nt][2], acc[mt][nt][3]);
            }
        }
        __syncthreads();

        // AV: out tile 64x64, K-dim = this tile's 64 cols
#pragma unroll
        for (int ks = 0; ks < 8; ks++) {
            int k0 = ks * 8;
            uint32_t a2[4], b2[4][2];
            {
                const float* pa = Sst + (warpM2 * 16 + gid) * 68 + k0 + tg;
                a2[0] = rna(pa[0]);
                a2[1] = rna(pa[8 * 68]);
                a2[2] = rna(pa[4]);
                a2[3] = rna(pa[8 * 68 + 4]);
            }
#pragma unroll
            for (int nt = 0; nt < 4; nt++) {
                const float* pb = Vb + (k0 + tg) * 72 + warpN2 * 32 + nt * 8 + gid;
                b2[nt][0] = rna(pb[0]);
                b2[nt][1] = rna(pb[4 * 72]);
            }
#pragma unroll
            for (int nt = 0; nt < 4; nt++)
                mma_tf32(oacc[nt], a2, b2[nt]);
        }
        __syncthreads();   // AV reads done before next tile restages Sst / K/V
    }

    // epilogue: oacc already normalized
    {
        int r = m0 + warpM2 * 16 + gid;
#pragma unroll
        for (int nt = 0; nt < 4; nt++) {
            int cc = warpN2 * 32 + nt * 8 + tg * 2;
            *reinterpret_cast<float2*>(out + ((size_t)(bb * L_ + r)) * D_ + h * 64 + cc) =
                make_float2(oacc[nt][0], oacc[nt][1]);
            *reinterpret_cast<float2*>(out + ((size_t)(bb * L_ + r + 8)) * D_ + h * 64 + cc) =
                make_float2(oacc[nt][2], oacc[nt][3]);
        }
    }
}

// ---------------------------------------------------------------------------
extern "C" void kernel_launch(void* const* d_in, const int* in_sizes, int n_in,
                              void* d_out, int out_size)
{
    const float* queries = (const float*)d_in[0];
    const float* keys    = (const float*)d_in[1];
    const float* values  = (const float*)d_in[2];
    const float* Wq      = (const float*)d_in[3];
    const float* bq      = (const float*)d_in[4];
    const float* Wk      = (const float*)d_in[5];
    const float* bk      = (const float*)d_in[6];
    const float* Wv      = (const float*)d_in[7];
    const float* bv      = (const float*)d_in[8];

    float* out  = (float*)d_out;
    float* attn = out + (size_t)B_ * L_ * D_;   // tuple order: (out, attn)

    static bool attr_set = false;
    if (!attr_set) {
        cudaFuncSetAttribute(proj_mma, cudaFuncAttributeMaxDynamicSharedMemorySize, PJ_SMEM);
        cudaFuncSetAttribute(fused64,  cudaFuncAttributeMaxDynamicSharedMemorySize, F_SMEM);
        attr_set = true;
    }

    proj_mma<<<dim3((B_ * L_) / 128, D_ / 128, 3), 256, PJ_SMEM>>>(
        queries, keys, values, Wq, Wk, Wv, bq, bk, bv);
    fused64<<<dim3(L_ / 64, B_ * H_), 256, F_SMEM>>>(attn, out);
}

// round 11
// speedup vs baseline: 1.2935x; 1.2935x over previous
#include <cuda_runtime.h>
#include <cuda_fp16.h>
#include <cstdint>

#define B_ 4
#define L_ 2048
#define D_ 512
#define H_ 8
#define E_ 64

// Projected Q/K in [B,H,L,E] fp32; V transposed fp16 [B,H,E,L].
__device__ __align__(256) float  g_q[B_ * H_ * L_ * E_];
__device__ __align__(256) float  g_k[B_ * H_ * L_ * E_];
__device__ __align__(256) __half g_vth[B_ * H_ * E_ * L_];
// Unnormalized exp(scores) scratch, fp16:
__device__ __align__(256) __half g_se[(size_t)B_ * H_ * L_ * L_];
// Per-row partial sums of exp(scores): [row_global][col_tile 0..15]
__device__ __align__(256) float g_psum[B_ * H_ * L_ * 16];

// ---------------------------------------------------------------------------
// helpers
// ---------------------------------------------------------------------------
__device__ __forceinline__ uint32_t smem_u32(const void* p) {
    uint32_t a;
    asm("{ .reg .u64 t; cvta.to.shared.u64 t, %1; cvt.u32.u64 %0, t; }"
        : "=r"(a) : "l"(p));
    return a;
}

__device__ __forceinline__ uint32_t rna(float x) {
    uint32_t r;
    asm("cvt.rna.tf32.f32 %0, %1;" : "=r"(r) : "f"(x));
    return r;
}

// tf32 m16n8k8
__device__ __forceinline__ void mma_tf32(float* d, const uint32_t* a, const uint32_t* b) {
    asm volatile(
        "mma.sync.aligned.m16n8k8.row.col.f32.tf32.tf32.f32 "
        "{%0,%1,%2,%3}, {%4,%5,%6,%7}, {%8,%9}, {%0,%1,%2,%3};"
        : "+f"(d[0]), "+f"(d[1]), "+f"(d[2]), "+f"(d[3])
        : "r"(a[0]), "r"(a[1]), "r"(a[2]), "r"(a[3]), "r"(b[0]), "r"(b[1]));
}

// fp16 m16n8k16, fp32 accum
__device__ __forceinline__ void mma_f16(float* d, const uint32_t* a, const uint32_t* b) {
    asm volatile(
        "mma.sync.aligned.m16n8k16.row.col.f32.f16.f16.f32 "
        "{%0,%1,%2,%3}, {%4,%5,%6,%7}, {%8,%9}, {%0,%1,%2,%3};"
        : "+f"(d[0]), "+f"(d[1]), "+f"(d[2]), "+f"(d[3])
        : "r"(a[0]), "r"(a[1]), "r"(a[2]), "r"(a[3]), "r"(b[0]), "r"(b[1]));
}

__device__ __forceinline__ void cp16(uint32_t dst, const void* src) {
    asm volatile("cp.async.cg.shared.global [%0], [%1], 16;"
                 :: "r"(dst), "l"(src) : "memory");
}
#define CP_COMMIT() asm volatile("cp.async.commit_group;" ::: "memory")
#define CP_WAIT(n)  asm volatile("cp.async.wait_group %0;" :: "n"(n) : "memory")

__device__ __forceinline__ void st_cs4(float* p, float4 v) {
    asm volatile("st.global.cs.v4.f32 [%0], {%1, %2, %3, %4};"
                 :: "l"(p), "f"(v.x), "f"(v.y), "f"(v.z), "f"(v.w) : "memory");
}
__device__ __forceinline__ void st_cs_h2(__half* p, uint32_t v) {
    asm volatile("st.global.cs.b32 [%0], %1;" :: "l"(p), "r"(v) : "memory");
}
__device__ __forceinline__ uint32_t pack_h2(float a, float b) {
    __half2 h = __floats2half2_rn(a, b);
    return *reinterpret_cast<uint32_t*>(&h);
}

// ---------------------------------------------------------------------------
// Kernel 1: QKV projection (1x tf32, RN-rounded operands).
// z=0/1 -> Q/K fp32 [B,H,L,E];  z=2 -> V transposed fp16 [B,H,E,L].
// CTA 128x128, grid (64, 4, 3), 256 thr.
// ---------------------------------------------------------------------------
static constexpr int PJ_XS = 128 * 36;
static constexpr int PJ_WS = 32 * 136;
static constexpr int PJ_SMEM = (2 * PJ_XS + 2 * PJ_WS) * 4;   // 71680 B

__global__ void __launch_bounds__(256, 2) proj_mma(
    const float* __restrict__ X0, const float* __restrict__ X1,
    const float* __restrict__ X2,
    const float* __restrict__ W0, const float* __restrict__ W1,
    const float* __restrict__ W2,
    const float* __restrict__ b0, const float* __restrict__ b1,
    const float* __restrict__ b2)
{
    extern __shared__ float smf[];
    float* Xs = smf;
    float* Ws = smf + 2 * PJ_XS;
    uint32_t sX = smem_u32(Xs), sW = smem_u32(Ws);

    int z = blockIdx.z;
    const float* X = (z == 0) ? X0 : (z == 1) ? X1 : X2;
    const float* W = (z == 0) ? W0 : (z == 1) ? W1 : W2;
    const float* bias = (z == 0) ? b0 : (z == 1) ? b1 : b2;

    int t = threadIdx.x;
    int lane = t & 31, wid = t >> 5;
    int gid = lane >> 2, tg = lane & 3;
    int warpM = wid >> 2, warpN = wid & 3;
    int m0 = blockIdx.x * 128, n0 = blockIdx.y * 128;

    float acc[4][4][4] = {};

    auto stage = [&](int kt, int buf) {
        int k0 = kt * 32;
#pragma unroll
        for (int i = 0; i < 4; i++) {
            int idx = t + i * 256;
            int row = idx >> 3, cc = (idx & 7) * 4;
            cp16(sX + (buf * PJ_XS + row * 36 + cc) * 4,
                 X + (size_t)(m0 + row) * D_ + k0 + cc);
        }
#pragma unroll
        for (int i = 0; i < 4; i++) {
            int idx = t + i * 256;
            int row = idx >> 5, cc = (idx & 31) * 4;
            cp16(sW + (buf * PJ_WS + row * 136 + cc) * 4,
                 W + (size_t)(k0 + row) * D_ + n0 + cc);
        }
    };

    stage(0, 0); CP_COMMIT();
    const int NIT = D_ / 32;                 // 16
    for (int kt = 0; kt < NIT; kt++) {
        int p = kt & 1;
        if (kt + 1 < NIT) { stage(kt + 1, p ^ 1); CP_COMMIT(); CP_WAIT(1); }
        else              { CP_WAIT(0); }
        __syncthreads();

        const float* Ab = Xs + p * PJ_XS;
        const float* Bb = Ws + p * PJ_WS;
#pragma unroll
        for (int ks = 0; ks < 4; ks++) {
            int k0 = ks * 8;
            uint32_t a[4][4], b[4][2];
#pragma unroll
            for (int mt = 0; mt < 4; mt++) {
                const float* pa = Ab + (warpM * 64 + mt * 16 + gid) * 36 + k0 + tg;
                a[mt][0] = rna(pa[0]);
                a[mt][1] = rna(pa[8 * 36]);
                a[mt][2] = rna(pa[4]);
                a[mt][3] = rna(pa[8 * 36 + 4]);
            }
#pragma unroll
            for (int nt = 0; nt < 4; nt++) {
                const float* pb = Bb + (k0 + tg) * 136 + warpN * 32 + nt * 8 + gid;
                b[nt][0] = rna(pb[0]);
                b[nt][1] = rna(pb[4 * 136]);
            }
#pragma unroll
            for (int mt = 0; mt < 4; mt++)
#pragma unroll
                for (int nt = 0; nt < 4; nt++)
                    mma_tf32(acc[mt][nt], a[mt], b[nt]);
        }
        __syncthreads();
    }

#pragma unroll
    for (int mt = 0; mt < 4; mt++) {
        int m = m0 + warpM * 64 + mt * 16 + gid;
        int bb = m >> 11;
        int l  = m & (L_ - 1);
#pragma unroll
        for (int nt = 0; nt < 4; nt++) {
            int n = n0 + warpN * 32 + nt * 8 + tg * 2;
            int h = n >> 6, e = n & 63;
            float2 bi = *reinterpret_cast<const float2*>(bias + n);
            float v0 = acc[mt][nt][0] + bi.x;
            float v1 = acc[mt][nt][1] + bi.y;
            float v2 = acc[mt][nt][2] + bi.x;
            float v3 = acc[mt][nt][3] + bi.y;
            if (z == 2) {
                __half* vt = g_vth + ((size_t)(bb * H_ + h)) * E_ * L_;
                vt[(size_t)e * L_ + l]           = __float2half(v0);
                vt[(size_t)(e + 1) * L_ + l]     = __float2half(v1);
                vt[(size_t)e * L_ + l + 8]       = __float2half(v2);
                vt[(size_t)(e + 1) * L_ + l + 8] = __float2half(v3);
            } else {
                float* dst = z ? g_k : g_q;
                *reinterpret_cast<float2*>(dst + (((size_t)(bb * H_ + h)) * L_ + l) * E_ + e) =
                    make_float2(v0, v1);
                *reinterpret_cast<float2*>(dst + (((size_t)(bb * H_ + h)) * L_ + l + 8) * E_ + e) =
                    make_float2(v2, v3);
            }
        }
    }
}

// ---------------------------------------------------------------------------
// Kernel 2: scores + exp (1x tf32).  Writes p = exp(scale*QK^T) (unnormalized)
// to g_se in FP16 (streaming), partial row sums (fp32) into g_psum.
// CTA 128x128, full K=64 resident.  grid (16,16,32), 256 threads.
// ---------------------------------------------------------------------------
static constexpr int S_SMEM = (2 * 128 * 68 + 4 * 128) * 4;   // 71680 B

__global__ void __launch_bounds__(256, 2) scores_mma()
{
    extern __shared__ float smf[];
    float* Qs = smf;
    float* Ks = smf + 128 * 68;
    float* red = smf + 2 * 128 * 68;         // [4][128]

    int t = threadIdx.x;
    int lane = t & 31, wid = t >> 5;
    int gid = lane >> 2, tg = lane & 3;
    int warpM = wid >> 2, warpN = wid & 3;
    int m0 = blockIdx.x * 128, n0 = blockIdx.y * 128, bh = blockIdx.z;

    const float* Q = g_q + (size_t)bh * L_ * E_;
    const float* K = g_k + (size_t)bh * L_ * E_;
    __half* Se = g_se + (size_t)bh * L_ * L_;

#pragma unroll
    for (int i = 0; i < 8; i++) {
        int idx = t + i * 256;
        int row = idx >> 4, cc = (idx & 15) * 4;
        *reinterpret_cast<float4*>(Qs + row * 68 + cc) =
            *reinterpret_cast<const float4*>(Q + (size_t)(m0 + row) * E_ + cc);
        *reinterpret_cast<float4*>(Ks + row * 68 + cc) =
            *reinterpret_cast<const float4*>(K + (size_t)(n0 + row) * E_ + cc);
    }
    __syncthreads();

    float acc[4][4][4] = {};
#pragma unroll
    for (int ks = 0; ks < 8; ks++) {
        int k0 = ks * 8;
        uint32_t a[4][4], b[4][2];
#pragma unroll
        for (int mt = 0; mt < 4; mt++) {
            const float* pa = Qs + (warpM * 64 + mt * 16 + gid) * 68 + k0 + tg;
            a[mt][0] = rna(pa[0]);
            a[mt][1] = rna(pa[8 * 68]);
            a[mt][2] = rna(pa[4]);
            a[mt][3] = rna(pa[8 * 68 + 4]);
        }
#pragma unroll
        for (int nt = 0; nt < 4; nt++) {
            const float* pb = Ks + (warpN * 32 + nt * 8 + gid) * 68 + k0 + tg;
            b[nt][0] = rna(pb[0]);
            b[nt][1] = rna(pb[4]);
        }
#pragma unroll
        for (int mt = 0; mt < 4; mt++)
#pragma unroll
            for (int nt = 0; nt < 4; nt++)
                mma_tf32(acc[mt][nt], a[mt], b[nt]);
    }

    const float scale = 0.125f;
    float rowpart[4][2] = {};
#pragma unroll
    for (int mt = 0; mt < 4; mt++) {
        int r = m0 + warpM * 64 + mt * 16 + gid;
#pragma unroll
        for (int nt = 0; nt < 4; nt++) {
            int cc = n0 + warpN * 32 + nt * 8 + tg * 2;
            float p0 = __expf(acc[mt][nt][0] * scale);
            float p1 = __expf(acc[mt][nt][1] * scale);
            float p2 = __expf(acc[mt][nt][2] * scale);
            float p3 = __expf(acc[mt][nt][3] * scale);
            st_cs_h2(Se + (size_t)r * L_ + cc, pack_h2(p0, p1));
            st_cs_h2(Se + (size_t)(r + 8) * L_ + cc, pack_h2(p2, p3));
            rowpart[mt][0] += p0 + p1;
            rowpart[mt][1] += p2 + p3;
        }
    }

#pragma unroll
    for (int mt = 0; mt < 4; mt++) {
#pragma unroll
        for (int half = 0; half < 2; half++) {
            float v = rowpart[mt][half];
            v += __shfl_xor_sync(0xffffffffu, v, 1);
            v += __shfl_xor_sync(0xffffffffu, v, 2);
            if (tg == 0)
                red[warpN * 128 + warpM * 64 + mt * 16 + gid + half * 8] = v;
        }
    }
    __syncthreads();
    if (t < 128) {
        float s = red[t] + red[128 + t] + red[256 + t] + red[384 + t];
        g_psum[((size_t)bh * L_ + m0 + t) * 16 + blockIdx.y] = s;
    }
}

// ---------------------------------------------------------------------------
// Kernel 3: AV via fp16 m16n8k16 MMA + normalize write-back.
// Reads fp16 unnorm exp from g_se, writes normalized fp32 attn (streaming),
// out = attn_norm @ V (V^T fp16 from g_vth).  CTA 128x64, 3-stage cp.async.
// grid (16,1,32), 256 threads, 8 warps (4M x 2N for out).
// SMEM: As[3][128][40] halfs | Vs[3][64][40] halfs | rowinv[128] f32 = 46592 B
// ---------------------------------------------------------------------------
static constexpr int AV_A = 128 * 40;     // halfs per A buffer
static constexpr int AV_B = 64 * 40;      // halfs per V buffer
static constexpr int AV_HB = (3 * AV_A + 3 * AV_B) * 2;   // 46080 bytes
static constexpr int AV_SMEM = AV_HB + 128 * 4;           // 46592 B

__global__ void __launch_bounds__(256, 2) av_mma(float* __restrict__ attn,
                                                 float* __restrict__ out)
{
    extern __shared__ char smc[];
    __half* As = reinterpret_cast<__half*>(smc);
    __half* Vs = As + 3 * AV_A;
    float* rowinv = reinterpret_cast<float*>(smc + AV_HB);
    uint32_t sA = smem_u32(As), sV = smem_u32(Vs);

    int t = threadIdx.x;
    int lane = t & 31, wid = t >> 5;
    int gid = lane >> 2, tg = lane & 3;
    int warpM = wid >> 1, warpN = wid & 1;
    int m0 = blockIdx.x * 128, bh = blockIdx.z;
    int bb = bh >> 3, h = bh & 7;

    const __half* Se = g_se + (size_t)bh * L_ * L_;
    const __half* Vt = g_vth + (size_t)bh * E_ * L_;
    float* A = attn + (size_t)bh * L_ * L_;

    float acc[2][4][4] = {};

    auto stage = [&](int kt, int buf) {
        int k0 = kt * 32;
        // A: 128 rows x 32 halfs (64 B/row -> 4 cp16/row, 512 total)
#pragma unroll
        for (int i = 0; i < 2; i++) {
            int idx = t + i * 256;
            int row = idx >> 2, g = idx & 3;
            cp16(sA + (buf * AV_A + row * 40 + g * 8) * 2,
                 Se + (size_t)(m0 + row) * L_ + k0 + g * 8);
        }
        // V^T: 64 rows (e) x 32 halfs (k) -> 256 cp16
        {
            int row = t >> 2, g = t & 3;
            cp16(sV + (buf * AV_B + row * 40 + g * 8) * 2,
                 Vt + (size_t)row * L_ + k0 + g * 8);
        }
    };

    const int NIT = L_ / 32;                  // 64
    stage(0, 0); CP_COMMIT();
    stage(1, 1); CP_COMMIT();

    if (t < 128) {
        const float* pp = g_psum + ((size_t)bh * L_ + m0 + t) * 16;
        float s = 0.f;
#pragma unroll
        for (int j = 0; j < 16; j++) s += pp[j];
        rowinv[t] = 1.0f / s;
    }

    for (int kt = 0; kt < NIT; kt++) {
        __syncthreads();
        if (kt + 2 < NIT) { stage(kt + 2, (kt + 2) % 3); CP_COMMIT(); CP_WAIT(2); }
        else if (kt + 1 < NIT) { CP_WAIT(1); }
        else { CP_WAIT(0); }
        __syncthreads();

        int p = kt % 3;
        const __half* Ab = As + p * AV_A;
        const __half* Vb = Vs + p * AV_B;

        // normalized fp32 write-back of this attn tile
        {
            int k0 = kt * 32;
#pragma unroll
            for (int i = 0; i < 2; i++) {
                int idx = t + i * 256;
                int row = idx >> 2, g = idx & 3;
                uint4 hv = *reinterpret_cast<const uint4*>(Ab + row * 40 + g * 8);
                float s = rowinv[row];
                float2 f0 = __half22float2(*reinterpret_cast<__half2*>(&hv.x));
                float2 f1 = __half22float2(*reinterpret_cast<__half2*>(&hv.y));
                float2 f2 = __half22float2(*reinterpret_cast<__half2*>(&hv.z));
                float2 f3 = __half22float2(*reinterpret_cast<__half2*>(&hv.w));
                st_cs4(A + (size_t)(m0 + row) * L_ + k0 + g * 8,
                       make_float4(f0.x * s, f0.y * s, f1.x * s, f1.y * s));
                st_cs4(A + (size_t)(m0 + row) * L_ + k0 + g * 8 + 4,
                       make_float4(f2.x * s, f2.y * s, f3.x * s, f3.y * s));
            }
        }

        // fp16 MMA: 2 k16 steps per 32-k tile
#pragma unroll
        for (int ks = 0; ks < 2; ks++) {
            int kk = ks * 16;
            uint32_t a[2][4], b[4][2];
#pragma unroll
            for (int mt = 0; mt < 2; mt++) {
                int row = warpM * 32 + mt * 16 + gid;
                a[mt][0] = *reinterpret_cast<const uint32_t*>(Ab + row * 40 + kk + tg * 2);
                a[mt][1] = *reinterpret_cast<const uint32_t*>(Ab + (row + 8) * 40 + kk + tg * 2);
                a[mt][2] = *reinterpret_cast<const uint32_t*>(Ab + row * 40 + kk + tg * 2 + 8);
                a[mt][3] = *reinterpret_cast<const uint32_t*>(Ab + (row + 8) * 40 + kk + tg * 2 + 8);
            }
#pragma unroll
            for (int nt = 0; nt < 4; nt++) {
                int n = warpN * 32 + nt * 8 + gid;
                b[nt][0] = *reinterpret_cast<const uint32_t*>(Vb + n * 40 + kk + tg * 2);
                b[nt][1] = *reinterpret_cast<const uint32_t*>(Vb + n * 40 + kk + tg * 2 + 8);
            }
#pragma unroll
            for (int mt = 0; mt < 2; mt++)
#pragma unroll
                for (int nt = 0; nt < 4; nt++)
                    mma_f16(acc[mt][nt], a[mt], b[nt]);
        }
    }

#pragma unroll
    for (int mt = 0; mt < 2; mt++) {
        int rloc = warpM * 32 + mt * 16 + gid;
        int r = m0 + rloc;
        float s0 = rowinv[rloc], s1 = rowinv[rloc + 8];
#pragma unroll
        for (int nt = 0; nt < 4; nt++) {
            int cc = warpN * 32 + nt * 8 + tg * 2;
            *reinterpret_cast<float2*>(out + ((size_t)(bb * L_ + r)) * D_ + h * 64 + cc) =
                make_float2(acc[mt][nt][0] * s0, acc[mt][nt][1] * s0);
            *reinterpret_cast<float2*>(out + ((size_t)(bb * L_ + r + 8)) * D_ + h * 64 + cc) =
                make_float2(acc[mt][nt][2] * s1, acc[mt][nt][3] * s1);
        }
    }
}

// ---------------------------------------------------------------------------
extern "C" void kernel_launch(void* const* d_in, const int* in_sizes, int n_in,
                              void* d_out, int out_size)
{
    const float* queries = (const float*)d_in[0];
    const float* keys    = (const float*)d_in[1];
    const float* values  = (const float*)d_in[2];
    const float* Wq      = (const float*)d_in[3];
    const float* bq      = (const float*)d_in[4];
    const float* Wk      = (const float*)d_in[5];
    const float* bk      = (const float*)d_in[6];
    const float* Wv      = (const float*)d_in[7];
    const float* bv      = (const float*)d_in[8];

    float* out  = (float*)d_out;
    float* attn = out + (size_t)B_ * L_ * D_;   // tuple order: (out, attn)

    static bool attr_set = false;
    if (!attr_set) {
        cudaFuncSetAttribute(proj_mma,   cudaFuncAttributeMaxDynamicSharedMemorySize, PJ_SMEM);
        cudaFuncSetAttribute(scores_mma, cudaFuncAttributeMaxDynamicSharedMemorySize, S_SMEM);
        cudaFuncSetAttribute(av_mma,     cudaFuncAttributeMaxDynamicSharedMemorySize, AV_SMEM);
        attr_set = true;
    }

    proj_mma<<<dim3((B_ * L_) / 128, D_ / 128, 3), 256, PJ_SMEM>>>(
        queries, keys, values, Wq, Wk, Wv, bq, bk, bv);
    scores_mma<<<dim3(L_ / 128, L_ / 128, B_ * H_), 256, S_SMEM>>>();
    av_mma<<<dim3(L_ / 128, 1, B_ * H_), 256, AV_SMEM>>>(attn, out);
}

// round 12
// speedup vs baseline: 1.4345x; 1.1090x over previous
#include <cuda_runtime.h>
#include <cuda_fp16.h>
#include <cstdint>

#define B_ 4
#define L_ 2048
#define D_ 512
#define H_ 8
#define E_ 64

// Projected Q/K fp16 [B,H,L,E]; V transposed fp16 [B,H,E,L].
__device__ __align__(256) __half g_qh[B_ * H_ * L_ * E_];
__device__ __align__(256) __half g_kh[B_ * H_ * L_ * E_];
__device__ __align__(256) __half g_vth[B_ * H_ * E_ * L_];
// Unnormalized exp(scores) scratch, fp16:
__device__ __align__(256) __half g_se[(size_t)B_ * H_ * L_ * L_];
// Per-row partial sums of exp(scores): [row_global][col_tile 0..15]
__device__ __align__(256) float g_psum[B_ * H_ * L_ * 16];

// ---------------------------------------------------------------------------
// helpers
// ---------------------------------------------------------------------------
__device__ __forceinline__ uint32_t smem_u32(const void* p) {
    uint32_t a;
    asm("{ .reg .u64 t; cvta.to.shared.u64 t, %1; cvt.u32.u64 %0, t; }"
        : "=r"(a) : "l"(p));
    return a;
}

__device__ __forceinline__ uint32_t rna(float x) {
    uint32_t r;
    asm("cvt.rna.tf32.f32 %0, %1;" : "=r"(r) : "f"(x));
    return r;
}

// tf32 m16n8k8 (projection only)
__device__ __forceinline__ void mma_tf32(float* d, const uint32_t* a, const uint32_t* b) {
    asm volatile(
        "mma.sync.aligned.m16n8k8.row.col.f32.tf32.tf32.f32 "
        "{%0,%1,%2,%3}, {%4,%5,%6,%7}, {%8,%9}, {%0,%1,%2,%3};"
        : "+f"(d[0]), "+f"(d[1]), "+f"(d[2]), "+f"(d[3])
        : "r"(a[0]), "r"(a[1]), "r"(a[2]), "r"(a[3]), "r"(b[0]), "r"(b[1]));
}

// fp16 m16n8k16, fp32 accum
__device__ __forceinline__ void mma_f16(float* d, const uint32_t* a, const uint32_t* b) {
    asm volatile(
        "mma.sync.aligned.m16n8k16.row.col.f32.f16.f16.f32 "
        "{%0,%1,%2,%3}, {%4,%5,%6,%7}, {%8,%9}, {%0,%1,%2,%3};"
        : "+f"(d[0]), "+f"(d[1]), "+f"(d[2]), "+f"(d[3])
        : "r"(a[0]), "r"(a[1]), "r"(a[2]), "r"(a[3]), "r"(b[0]), "r"(b[1]));
}

__device__ __forceinline__ void cp16(uint32_t dst, const void* src) {
    asm volatile("cp.async.cg.shared.global [%0], [%1], 16;"
                 :: "r"(dst), "l"(src) : "memory");
}
#define CP_COMMIT() asm volatile("cp.async.commit_group;" ::: "memory")
#define CP_WAIT(n)  asm volatile("cp.async.wait_group %0;" :: "n"(n) : "memory")

__device__ __forceinline__ void st_cs4(float* p, float4 v) {
    asm volatile("st.global.cs.v4.f32 [%0], {%1, %2, %3, %4};"
                 :: "l"(p), "f"(v.x), "f"(v.y), "f"(v.z), "f"(v.w) : "memory");
}
__device__ __forceinline__ void st_cs_h2(__half* p, uint32_t v) {
    asm volatile("st.global.cs.b32 [%0], %1;" :: "l"(p), "r"(v) : "memory");
}
__device__ __forceinline__ uint32_t pack_h2(float a, float b) {
    __half2 h = __floats2half2_rn(a, b);
    return *reinterpret_cast<uint32_t*>(&h);
}

// ---------------------------------------------------------------------------
// Kernel 1: QKV projection (1x tf32, RN-rounded operands).
// z=0/1 -> Q/K fp16 [B,H,L,E];  z=2 -> V transposed fp16 [B,H,E,L].
// CTA 128x128, grid (64, 4, 3), 256 thr.
// ---------------------------------------------------------------------------
static constexpr int PJ_XS = 128 * 36;
static constexpr int PJ_WS = 32 * 136;
static constexpr int PJ_SMEM = (2 * PJ_XS + 2 * PJ_WS) * 4;   // 71680 B

__global__ void __launch_bounds__(256, 2) proj_mma(
    const float* __restrict__ X0, const float* __restrict__ X1,
    const float* __restrict__ X2,
    const float* __restrict__ W0, const float* __restrict__ W1,
    const float* __restrict__ W2,
    const float* __restrict__ b0, const float* __restrict__ b1,
    const float* __restrict__ b2)
{
    extern __shared__ float smf[];
    float* Xs = smf;
    float* Ws = smf + 2 * PJ_XS;
    uint32_t sX = smem_u32(Xs), sW = smem_u32(Ws);

    int z = blockIdx.z;
    const float* X = (z == 0) ? X0 : (z == 1) ? X1 : X2;
    const float* W = (z == 0) ? W0 : (z == 1) ? W1 : W2;
    const float* bias = (z == 0) ? b0 : (z == 1) ? b1 : b2;

    int t = threadIdx.x;
    int lane = t & 31, wid = t >> 5;
    int gid = lane >> 2, tg = lane & 3;
    int warpM = wid >> 2, warpN = wid & 3;
    int m0 = blockIdx.x * 128, n0 = blockIdx.y * 128;

    float acc[4][4][4] = {};

    auto stage = [&](int kt, int buf) {
        int k0 = kt * 32;
#pragma unroll
        for (int i = 0; i < 4; i++) {
            int idx = t + i * 256;
            int row = idx >> 3, cc = (idx & 7) * 4;
            cp16(sX + (buf * PJ_XS + row * 36 + cc) * 4,
                 X + (size_t)(m0 + row) * D_ + k0 + cc);
        }
#pragma unroll
        for (int i = 0; i < 4; i++) {
            int idx = t + i * 256;
            int row = idx >> 5, cc = (idx & 31) * 4;
            cp16(sW + (buf * PJ_WS + row * 136 + cc) * 4,
                 W + (size_t)(k0 + row) * D_ + n0 + cc);
        }
    };

    stage(0, 0); CP_COMMIT();
    const int NIT = D_ / 32;                 // 16
    for (int kt = 0; kt < NIT; kt++) {
        int p = kt & 1;
        if (kt + 1 < NIT) { stage(kt + 1, p ^ 1); CP_COMMIT(); CP_WAIT(1); }
        else              { CP_WAIT(0); }
        __syncthreads();

        const float* Ab = Xs + p * PJ_XS;
        const float* Bb = Ws + p * PJ_WS;
#pragma unroll
        for (int ks = 0; ks < 4; ks++) {
            int k0 = ks * 8;
            uint32_t a[4][4], b[4][2];
#pragma unroll
            for (int mt = 0; mt < 4; mt++) {
                const float* pa = Ab + (warpM * 64 + mt * 16 + gid) * 36 + k0 + tg;
                a[mt][0] = rna(pa[0]);
                a[mt][1] = rna(pa[8 * 36]);
                a[mt][2] = rna(pa[4]);
                a[mt][3] = rna(pa[8 * 36 + 4]);
            }
#pragma unroll
            for (int nt = 0; nt < 4; nt++) {
                const float* pb = Bb + (k0 + tg) * 136 + warpN * 32 + nt * 8 + gid;
                b[nt][0] = rna(pb[0]);
                b[nt][1] = rna(pb[4 * 136]);
            }
#pragma unroll
            for (int mt = 0; mt < 4; mt++)
#pragma unroll
                for (int nt = 0; nt < 4; nt++)
                    mma_tf32(acc[mt][nt], a[mt], b[nt]);
        }
        __syncthreads();
    }

#pragma unroll
    for (int mt = 0; mt < 4; mt++) {
        int m = m0 + warpM * 64 + mt * 16 + gid;
        int bb = m >> 11;
        int l  = m & (L_ - 1);
#pragma unroll
        for (int nt = 0; nt < 4; nt++) {
            int n = n0 + warpN * 32 + nt * 8 + tg * 2;
            int h = n >> 6, e = n & 63;
            float2 bi = *reinterpret_cast<const float2*>(bias + n);
            float v0 = acc[mt][nt][0] + bi.x;
            float v1 = acc[mt][nt][1] + bi.y;
            float v2 = acc[mt][nt][2] + bi.x;
            float v3 = acc[mt][nt][3] + bi.y;
            if (z == 2) {
                __half* vt = g_vth + ((size_t)(bb * H_ + h)) * E_ * L_;
                vt[(size_t)e * L_ + l]           = __float2half(v0);
                vt[(size_t)(e + 1) * L_ + l]     = __float2half(v1);
                vt[(size_t)e * L_ + l + 8]       = __float2half(v2);
                vt[(size_t)(e + 1) * L_ + l + 8] = __float2half(v3);
            } else {
                __half* dst = z ? g_kh : g_qh;
                *reinterpret_cast<uint32_t*>(dst + (((size_t)(bb * H_ + h)) * L_ + l) * E_ + e) =
                    pack_h2(v0, v1);
                *reinterpret_cast<uint32_t*>(dst + (((size_t)(bb * H_ + h)) * L_ + l + 8) * E_ + e) =
                    pack_h2(v2, v3);
            }
        }
    }
}

// ---------------------------------------------------------------------------
// Kernel 2: scores + exp via fp16 m16n8k16.  Writes p = exp(scale*QK^T)
// (unnormalized) to g_se in FP16 (streaming), row psums (fp32) to g_psum.
// CTA 128x128, full K=64 resident, no rna in hot path.
// grid (16,16,32), 256 threads.
// SMEM: Qs[128][72] halfs | Ks[128][72] halfs | red[512] f32 = 38912 B
// ---------------------------------------------------------------------------
static constexpr int SQ = 72;                    // half stride
static constexpr int S_HB = 2 * 128 * SQ * 2;    // 36864 bytes
static constexpr int S_SMEM = S_HB + 512 * 4;    // 38912 B

__global__ void __launch_bounds__(256, 2) scores_mma()
{
    extern __shared__ char smc[];
    __half* Qs = reinterpret_cast<__half*>(smc);
    __half* Ks = Qs + 128 * SQ;
    float* red = reinterpret_cast<float*>(smc + S_HB);
    uint32_t sQ = smem_u32(Qs), sK = smem_u32(Ks);

    int t = threadIdx.x;
    int lane = t & 31, wid = t >> 5;
    int gid = lane >> 2, tg = lane & 3;
    int warpM = wid >> 2, warpN = wid & 3;
    int m0 = blockIdx.x * 128, n0 = blockIdx.y * 128, bh = blockIdx.z;

    const __half* Q = g_qh + (size_t)bh * L_ * E_;
    const __half* K = g_kh + (size_t)bh * L_ * E_;
    __half* Se = g_se + (size_t)bh * L_ * L_;

    // load Q/K tiles: 128 rows x 64 halfs = 128 B/row = 8 cp16/row
#pragma unroll
    for (int i = 0; i < 4; i++) {
        int idx = t + i * 256;                 // 1024 each
        int row = idx >> 3, g = idx & 7;
        cp16(sQ + (row * SQ + g * 8) * 2, Q + (size_t)(m0 + row) * E_ + g * 8);
        cp16(sK + (row * SQ + g * 8) * 2, K + (size_t)(n0 + row) * E_ + g * 8);
    }
    CP_COMMIT(); CP_WAIT(0);
    __syncthreads();

    float acc[4][4][4] = {};
#pragma unroll
    for (int ks = 0; ks < 4; ks++) {
        int k0 = ks * 16;
        uint32_t a[4][4], b[4][2];
#pragma unroll
        for (int mt = 0; mt < 4; mt++) {
            const __half* pa = Qs + (warpM * 64 + mt * 16 + gid) * SQ + k0 + tg * 2;
            a[mt][0] = *reinterpret_cast<const uint32_t*>(pa);
            a[mt][1] = *reinterpret_cast<const uint32_t*>(pa + 8 * SQ);
            a[mt][2] = *reinterpret_cast<const uint32_t*>(pa + 8);
            a[mt][3] = *reinterpret_cast<const uint32_t*>(pa + 8 * SQ + 8);
        }
#pragma unroll
        for (int nt = 0; nt < 4; nt++) {
            const __half* pb = Ks + (warpN * 32 + nt * 8 + gid) * SQ + k0 + tg * 2;
            b[nt][0] = *reinterpret_cast<const uint32_t*>(pb);
            b[nt][1] = *reinterpret_cast<const uint32_t*>(pb + 8);
        }
#pragma unroll
        for (int mt = 0; mt < 4; mt++)
#pragma unroll
            for (int nt = 0; nt < 4; nt++)
                mma_f16(acc[mt][nt], a[mt], b[nt]);
    }

    const float scale = 0.125f;
    float rowpart[4][2] = {};
#pragma unroll
    for (int mt = 0; mt < 4; mt++) {
        int r = m0 + warpM * 64 + mt * 16 + gid;
#pragma unroll
        for (int nt = 0; nt < 4; nt++) {
            int cc = n0 + warpN * 32 + nt * 8 + tg * 2;
            float p0 = __expf(acc[mt][nt][0] * scale);
            float p1 = __expf(acc[mt][nt][1] * scale);
            float p2 = __expf(acc[mt][nt][2] * scale);
            float p3 = __expf(acc[mt][nt][3] * scale);
            st_cs_h2(Se + (size_t)r * L_ + cc, pack_h2(p0, p1));
            st_cs_h2(Se + (size_t)(r + 8) * L_ + cc, pack_h2(p2, p3));
            rowpart[mt][0] += p0 + p1;
            rowpart[mt][1] += p2 + p3;
        }
    }

#pragma unroll
    for (int mt = 0; mt < 4; mt++) {
#pragma unroll
        for (int half = 0; half < 2; half++) {
            float v = rowpart[mt][half];
            v += __shfl_xor_sync(0xffffffffu, v, 1);
            v += __shfl_xor_sync(0xffffffffu, v, 2);
            if (tg == 0)
                red[warpN * 128 + warpM * 64 + mt * 16 + gid + half * 8] = v;
        }
    }
    __syncthreads();
    if (t < 128) {
        float s = red[t] + red[128 + t] + red[256 + t] + red[384 + t];
        g_psum[((size_t)bh * L_ + m0 + t) * 16 + blockIdx.y] = s;
    }
}

// ---------------------------------------------------------------------------
// Kernel 3: AV via fp16 m16n8k16 MMA + normalize write-back.
// Reads fp16 unnorm exp from g_se, writes normalized fp32 attn (streaming),
// out = attn_norm @ V (V^T fp16 from g_vth).  CTA 128x64, 3-stage cp.async.
// grid (16,1,32), 256 threads, 8 warps (4M x 2N for out).
// SMEM: As[3][128][40] halfs | Vs[3][64][40] halfs | rowinv[128] f32 = 46592 B
// ---------------------------------------------------------------------------
static constexpr int AV_A = 128 * 40;
static constexpr int AV_B = 64 * 40;
static constexpr int AV_HB = (3 * AV_A + 3 * AV_B) * 2;   // 46080 bytes
static constexpr int AV_SMEM = AV_HB + 128 * 4;           // 46592 B

__global__ void __launch_bounds__(256, 2) av_mma(float* __restrict__ attn,
                                                 float* __restrict__ out)
{
    extern __shared__ char smc[];
    __half* As = reinterpret_cast<__half*>(smc);
    __half* Vs = As + 3 * AV_A;
    float* rowinv = reinterpret_cast<float*>(smc + AV_HB);
    uint32_t sA = smem_u32(As), sV = smem_u32(Vs);

    int t = threadIdx.x;
    int lane = t & 31, wid = t >> 5;
    int gid = lane >> 2, tg = lane & 3;
    int warpM = wid >> 1, warpN = wid & 1;
    int m0 = blockIdx.x * 128, bh = blockIdx.z;
    int bb = bh >> 3, h = bh & 7;

    const __half* Se = g_se + (size_t)bh * L_ * L_;
    const __half* Vt = g_vth + (size_t)bh * E_ * L_;
    float* A = attn + (size_t)bh * L_ * L_;

    float acc[2][4][4] = {};

    auto stage = [&](int kt, int buf) {
        int k0 = kt * 32;
#pragma unroll
        for (int i = 0; i < 2; i++) {
            int idx = t + i * 256;
            int row = idx >> 2, g = idx & 3;
            cp16(sA + (buf * AV_A + row * 40 + g * 8) * 2,
                 Se + (size_t)(m0 + row) * L_ + k0 + g * 8);
        }
        {
            int row = t >> 2, g = t & 3;
            cp16(sV + (buf * AV_B + row * 40 + g * 8) * 2,
                 Vt + (size_t)row * L_ + k0 + g * 8);
        }
    };

    const int NIT = L_ / 32;                  // 64
    stage(0, 0); CP_COMMIT();
    stage(1, 1); CP_COMMIT();

    if (t < 128) {
        const float* pp = g_psum + ((size_t)bh * L_ + m0 + t) * 16;
        float s = 0.f;
#pragma unroll
        for (int j = 0; j < 16; j++) s += pp[j];
        rowinv[t] = 1.0f / s;
    }

    for (int kt = 0; kt < NIT; kt++) {
        __syncthreads();
        if (kt + 2 < NIT) { stage(kt + 2, (kt + 2) % 3); CP_COMMIT(); CP_WAIT(2); }
        else if (kt + 1 < NIT) { CP_WAIT(1); }
        else { CP_WAIT(0); }
        __syncthreads();

        int p = kt % 3;
        const __half* Ab = As + p * AV_A;
        const __half* Vb = Vs + p * AV_B;

        // normalized fp32 write-back of this attn tile
        {
            int k0 = kt * 32;
#pragma unroll
            for (int i = 0; i < 2; i++) {
                int idx = t + i * 256;
                int row = idx >> 2, g = idx & 3;
                uint4 hv = *reinterpret_cast<const uint4*>(Ab + row * 40 + g * 8);
                float s = rowinv[row];
                float2 f0 = __half22float2(*reinterpret_cast<__half2*>(&hv.x));
                float2 f1 = __half22float2(*reinterpret_cast<__half2*>(&hv.y));
                float2 f2 = __half22float2(*reinterpret_cast<__half2*>(&hv.z));
                float2 f3 = __half22float2(*reinterpret_cast<__half2*>(&hv.w));
                st_cs4(A + (size_t)(m0 + row) * L_ + k0 + g * 8,
                       make_float4(f0.x * s, f0.y * s, f1.x * s, f1.y * s));
                st_cs4(A + (size_t)(m0 + row) * L_ + k0 + g * 8 + 4,
                       make_float4(f2.x * s, f2.y * s, f3.x * s, f3.y * s));
            }
        }

#pragma unroll
        for (int ks = 0; ks < 2; ks++) {
            int kk = ks * 16;
            uint32_t a[2][4], b[4][2];
#pragma unroll
            for (int mt = 0; mt < 2; mt++) {
                int row = warpM * 32 + mt * 16 + gid;
                a[mt][0] = *reinterpret_cast<const uint32_t*>(Ab + row * 40 + kk + tg * 2);
                a[mt][1] = *reinterpret_cast<const uint32_t*>(Ab + (row + 8) * 40 + kk + tg * 2);
                a[mt][2] = *reinterpret_cast<const uint32_t*>(Ab + row * 40 + kk + tg * 2 + 8);
                a[mt][3] = *reinterpret_cast<const uint32_t*>(Ab + (row + 8) * 40 + kk + tg * 2 + 8);
            }
#pragma unroll
            for (int nt = 0; nt < 4; nt++) {
                int n = warpN * 32 + nt * 8 + gid;
                b[nt][0] = *reinterpret_cast<const uint32_t*>(Vb + n * 40 + kk + tg * 2);
                b[nt][1] = *reinterpret_cast<const uint32_t*>(Vb + n * 40 + kk + tg * 2 + 8);
            }
#pragma unroll
            for (int mt = 0; mt < 2; mt++)
#pragma unroll
                for (int nt = 0; nt < 4; nt++)
                    mma_f16(acc[mt][nt], a[mt], b[nt]);
        }
    }

#pragma unroll
    for (int mt = 0; mt < 2; mt++) {
        int rloc = warpM * 32 + mt * 16 + gid;
        int r = m0 + rloc;
        float s0 = rowinv[rloc], s1 = rowinv[rloc + 8];
#pragma unroll
        for (int nt = 0; nt < 4; nt++) {
            int cc = warpN * 32 + nt * 8 + tg * 2;
            *reinterpret_cast<float2*>(out + ((size_t)(bb * L_ + r)) * D_ + h * 64 + cc) =
                make_float2(acc[mt][nt][0] * s0, acc[mt][nt][1] * s0);
            *reinterpret_cast<float2*>(out + ((size_t)(bb * L_ + r + 8)) * D_ + h * 64 + cc) =
                make_float2(acc[mt][nt][2] * s1, acc[mt][nt][3] * s1);
        }
    }
}

// ---------------------------------------------------------------------------
extern "C" void kernel_launch(void* const* d_in, const int* in_sizes, int n_in,
                              void* d_out, int out_size)
{
    const float* queries = (const float*)d_in[0];
    const float* keys    = (const float*)d_in[1];
    const float* values  = (const float*)d_in[2];
    const float* Wq      = (const float*)d_in[3];
    const float* bq      = (const float*)d_in[4];
    const float* Wk      = (const float*)d_in[5];
    const float* bk      = (const float*)d_in[6];
    const float* Wv      = (const float*)d_in[7];
    const float* bv      = (const float*)d_in[8];

    float* out  = (float*)d_out;
    float* attn = out + (size_t)B_ * L_ * D_;   // tuple order: (out, attn)

    static bool attr_set = false;
    if (!attr_set) {
        cudaFuncSetAttribute(proj_mma,   cudaFuncAttributeMaxDynamicSharedMemorySize, PJ_SMEM);
        cudaFuncSetAttribute(scores_mma, cudaFuncAttributeMaxDynamicSharedMemorySize, S_SMEM);
        cudaFuncSetAttribute(av_mma,     cudaFuncAttributeMaxDynamicSharedMemorySize, AV_SMEM);
        attr_set = true;
    }

    proj_mma<<<dim3((B_ * L_) / 128, D_ / 128, 3), 256, PJ_SMEM>>>(
        queries, keys, values, Wq, Wk, Wv, bq, bk, bv);
    scores_mma<<<dim3(L_ / 128, L_ / 128, B_ * H_), 256, S_SMEM>>>();
    av_mma<<<dim3(L_ / 128, 1, B_ * H_), 256, AV_SMEM>>>(attn, out);
}